// round 1
// baseline (speedup 1.0000x reference)
#include <cuda_runtime.h>
#include <math.h>

#define S    64
#define DMAX 32
#define TT   1024
#define BB   32
#define FF   64
#define CC   128
#define NEGV  (-1e30f)
#define LOGPI (-4.15888308335967186f)   /* -log(64) */
#define LOG2PI (1.83787706640934534f)

// ---------------- scratch (__device__ globals; no allocation allowed) ----------------
__device__ __align__(16) float g_h[10240];       // layer-1 hidden: hA[4096] hD[2048] hE[4096]
__device__ __align__(16) float g_delta[10240];   // layer-2 out:    dA[4096] dD[2048] dE[4096]
__device__ __align__(16) float g_A[S * S];       // softmax probs A[s'][s]
__device__ __align__(16) float g_logDur[DMAX * S];  // [d][s]
__device__ __align__(16) float g_coefA[FF * S];  // [f][s] = -0.5/var
__device__ __align__(16) float g_coefB[FF * S];  // [f][s] = mu_c/var
__device__ __align__(16) float g_constS[S];
__device__ __align__(16) float g_logB[(size_t)BB * TT * S];   // [b][t][s], 8 MB

// ---------------- kernel 1a: hidden = tanh(W1 @ ctx + b1), warp per row ----------------
__global__ void k_layer1(const float* __restrict__ ctx,
                         const float* __restrict__ wA, const float* __restrict__ bA,
                         const float* __restrict__ wD, const float* __restrict__ bD,
                         const float* __restrict__ wE, const float* __restrict__ bE) {
    int warp = (blockIdx.x * blockDim.x + threadIdx.x) >> 5;
    int lane = threadIdx.x & 31;
    if (warp >= 10240) return;
    const float* w; const float* bb; int r;
    if (warp < 4096)      { w = wA; bb = bA; r = warp; }
    else if (warp < 6144) { w = wD; bb = bD; r = warp - 4096; }
    else                  { w = wE; bb = bE; r = warp - 6144; }
    const float4* wr = (const float4*)(w + (size_t)r * CC);
    float4 wv = wr[lane];
    float4 cv = ((const float4*)ctx)[lane];
    float sum = wv.x * cv.x + wv.y * cv.y + wv.z * cv.z + wv.w * cv.w;
    #pragma unroll
    for (int o = 16; o; o >>= 1) sum += __shfl_xor_sync(0xffffffffu, sum, o);
    if (lane == 0) g_h[warp] = tanhf(sum + bb[r]);
}

// ---------------- kernel 1b: delta = W2 @ h + b2, warp per row, h staged in smem ----------------
__global__ void k_layer2(const float* __restrict__ w2A, const float* __restrict__ b2A,
                         const float* __restrict__ w2D, const float* __restrict__ b2D,
                         const float* __restrict__ w2E, const float* __restrict__ b2E) {
    __shared__ __align__(16) float sh[4096];
    int rowBase = blockIdx.x * 8;
    const float* w2; const float* b2; int N, hoff, lr;
    if (rowBase < 4096)      { w2 = w2A; b2 = b2A; N = 4096; hoff = 0;    lr = rowBase; }
    else if (rowBase < 6144) { w2 = w2D; b2 = b2D; N = 2048; hoff = 4096; lr = rowBase - 4096; }
    else                     { w2 = w2E; b2 = b2E; N = 4096; hoff = 6144; lr = rowBase - 6144; }
    for (int i = threadIdx.x; i < N / 4; i += 256)
        ((float4*)sh)[i] = ((const float4*)(g_h + hoff))[i];
    __syncthreads();
    int wid = threadIdx.x >> 5, lane = threadIdx.x & 31;
    int r = lr + wid;
    const float4* wr = (const float4*)(w2 + (size_t)r * N);
    float sum = 0.f;
    for (int k4 = lane; k4 < N / 4; k4 += 32) {
        float4 wv = wr[k4];
        float4 hv = ((const float4*)sh)[k4];
        sum += wv.x * hv.x + wv.y * hv.y + wv.z * hv.z + wv.w * hv.w;
    }
    #pragma unroll
    for (int o = 16; o; o >>= 1) sum += __shfl_xor_sync(0xffffffffu, sum, o);
    if (lane == 0) g_delta[rowBase + wid] = sum + b2[r];
}

// ---------------- kernel 1c: derived parameters (A probs, logDur, emission coeffs) ----------------
__global__ void k_params(const float* __restrict__ A_logits, const float* __restrict__ D_logits,
                         const float* __restrict__ mu, const float* __restrict__ log_var) {
    int s = threadIdx.x;   // 64 threads
    // ---- A row s: softmax probabilities (stored, used directly in trans GEMM) ----
    const float* dA = g_delta;
    float m = -1e30f;
    for (int j = 0; j < S; j++) {
        float l = A_logits[s * S + j] + 0.1f * tanhf(dA[s * S + j]);
        m = fmaxf(m, l);
    }
    float sum = 0.f;
    for (int j = 0; j < S; j++)
        sum += __expf(A_logits[s * S + j] + 0.1f * tanhf(dA[s * S + j]) - m);
    float inv = 1.f / sum;
    for (int j = 0; j < S; j++)
        g_A[s * S + j] = __expf(A_logits[s * S + j] + 0.1f * tanhf(dA[s * S + j]) - m) * inv;
    // ---- Dur row s: log-softmax, transposed to [d][s] ----
    const float* dD = g_delta + 4096;
    m = -1e30f;
    for (int d = 0; d < DMAX; d++) {
        float l = D_logits[s * DMAX + d] + 0.1f * tanhf(dD[s * DMAX + d]);
        m = fmaxf(m, l);
    }
    sum = 0.f;
    for (int d = 0; d < DMAX; d++)
        sum += __expf(D_logits[s * DMAX + d] + 0.1f * tanhf(dD[s * DMAX + d]) - m);
    float lsum = __logf(sum);
    for (int d = 0; d < DMAX; d++) {
        float l = D_logits[s * DMAX + d] + 0.1f * tanhf(dD[s * DMAX + d]);
        g_logDur[d * S + s] = l - m - lsum;
    }
    // ---- emission: mu_c, var -> quadratic coefficients (transposed [f][s]) ----
    const float* dE = g_delta + 6144;
    float c = 0.f;
    for (int f = 0; f < FF; f++) {
        float mc = mu[s * FF + f] + 0.1f * tanhf(dE[s * FF + f]);
        float z  = log_var[s * FF + f];
        float sp = fmaxf(z, 0.f) + log1pf(__expf(-fabsf(z)));   // stable softplus
        float var = sp + 0.001f;
        float iv = 1.f / var;
        g_coefA[f * S + s] = -0.5f * iv;
        g_coefB[f * S + s] = mc * iv;
        c += mc * mc * iv + __logf(var);
    }
    g_constS[s] = -0.5f * (c + (float)FF * LOG2PI);
}

// ---------------- kernel 2: logB[b][t][s] = sum_f x*(a*x + c) + const[s] ----------------
__global__ void __launch_bounds__(1024) k_logB(const float* __restrict__ x) {
    __shared__ float scA[FF * S];
    __shared__ float scB[FF * S];
    __shared__ float sx[16 * FF];
    __shared__ float scs[S];
    int tid = threadIdx.x;
    for (int i = tid; i < FF * S; i += 1024) { scA[i] = g_coefA[i]; scB[i] = g_coefB[i]; }
    if (tid < S) scs[tid] = g_constS[tid];
    int b = blockIdx.y, t0 = blockIdx.x * 16;
    for (int i = tid; i < 16 * FF; i += 1024)
        sx[i] = x[((size_t)b * TT + t0) * FF + i];
    __syncthreads();
    int s = tid & 63, tl = tid >> 6;
    float acc = scs[s];
    #pragma unroll
    for (int f = 0; f < FF; f++) {
        float xv = sx[tl * FF + f];
        acc = fmaf(xv, fmaf(scA[f * S + s], xv, scB[f * S + s]), acc);
    }
    g_logB[((size_t)b * TT + t0 + tl) * S + s] = acc;
}

// ---------------- kernel 3: sequential HSMM forward recurrence, one block per batch ----------------
// Key restructurings vs reference:
//  (a) trans[d] at step t == trans computed from alpha_{t-d}: memoized in a depth-32 ring.
//  (b) trans lse done as exp-GEMM: m_a + log(sum_{s'} exp(alpha[s']-m_a) * A[s',s]).
//  (c) Ccum kept as 33-deep smem ring (Ccum[0]=0 slot preserved exactly as long as needed).
__global__ void __launch_bounds__(128, 1) k_recur(float* __restrict__ out) {
    __shared__ float sCc[33 * S];       // Ccum ring, slot = (t+1) % 33
    __shared__ float sTr[DMAX * S];     // trans ring, slot = t & 31
    __shared__ float sAlpha[S];
    __shared__ float sE[S];
    __shared__ float sPm[2][S], sPs[2][S], sDot[2][S];
    __shared__ float sMa[2];
    int tid = threadIdx.x;
    int s = tid & 63, g = tid >> 6;     // g in {0,1}: splits d-range and s'-range
    int b = blockIdx.x;

    // Per-thread constants in registers (removes smem crossbar traffic in hot loop)
    float rLD[16], rA[32];
    #pragma unroll
    for (int i = 0; i < 16; i++) rLD[i] = g_logDur[(g * 16 + i) * S + s];
    #pragma unroll
    for (int j = 0; j < 32; j++) rA[j] = g_A[(g * 32 + j) * S + s];

    if (tid < S) sCc[s] = 0.f;          // slot 0 holds Ccum[0] = 0
    float ccum = 0.f;
    const float* lbp = g_logB + (size_t)b * TT * S + s;
    float lb = (tid < S) ? lbp[0] : 0.f;
    int cur = 1;                         // (t+1) % 33
    float m_a = 0.f;
    __syncthreads();

    for (int t = 0; t < TT; t++) {
        // Ccum[t+1] = Ccum[t] + logB[t]
        if (tid < S) { ccum += lb; sCc[cur * S + s] = ccum; }
        float lb_next = (tid < S && t + 1 < TT) ? lbp[(t + 1) * S] : 0.f;   // prefetch
        __syncthreads();                                   // A: Ccum + prev trans visible

        // --- stage 1: alpha_t[s] = lse_d( prev_d + logDur[d][s] + seg[d][s] ), split over g ---
        float ccnow = sCc[cur * S + s];
        float v[16];
        float m = NEGV;
        #pragma unroll
        for (int i = 0; i < 16; i++) {
            int d = g * 16 + i + 1;
            float val;
            if (d <= t) {
                int cs = cur - d; if (cs < 0) cs += 33;
                val = sTr[((t - d) & 31) * S + s] + rLD[i] + (ccnow - sCc[cs * S + s]);
            } else if (d == t + 1) {
                val = LOGPI + rLD[i] + ccnow;              // Ccum[0] = 0
            } else {
                val = NEGV;
            }
            v[i] = val;
            m = fmaxf(m, val);
        }
        float sm = 0.f;
        #pragma unroll
        for (int i = 0; i < 16; i++) sm += __expf(v[i] - m);
        sPm[g][s] = m; sPs[g][s] = sm;
        __syncthreads();                                   // B

        if (g == 0) {                                      // tid 0..63 (warps 0,1 fully active)
            float m0 = sPm[0][s], m1 = sPm[1][s];
            float mm = fmaxf(m0, m1);
            float alpha = mm + __logf(sPs[0][s] * __expf(m0 - mm) + sPs[1][s] * __expf(m1 - mm));
            sAlpha[s] = alpha;
            float wm = alpha;
            #pragma unroll
            for (int o = 16; o; o >>= 1) wm = fmaxf(wm, __shfl_xor_sync(0xffffffffu, wm, o));
            if ((s & 31) == 0) sMa[s >> 5] = wm;
        }
        __syncthreads();                                   // C

        m_a = fmaxf(sMa[0], sMa[1]);
        if (tid < S) sE[s] = __expf(sAlpha[s] - m_a);
        __syncthreads();                                   // D

        // --- stage 2: trans[s] = m_a + log( sum_{s'} e[s'] * A[s'][s] ), split over g ---
        float acc = 0.f;
        #pragma unroll
        for (int j = 0; j < 32; j++) acc = fmaf(sE[g * 32 + j], rA[j], acc);
        sDot[g][s] = acc;
        __syncthreads();                                   // E

        if (tid < S) sTr[(t & 31) * S + s] = m_a + __logf(sDot[0][s] + sDot[1][s]);

        cur++; if (cur == 33) cur = 0;
        lb = lb_next;
    }
    __syncthreads();
    if (tid == 0) {
        float ssum = 0.f;
        for (int j = 0; j < S; j++) ssum += sE[j];
        out[b] = m_a + __logf(ssum);                       // lse over s of alpha_{T-1}
    }
}

// ---------------- launch ----------------
extern "C" void kernel_launch(void* const* d_in, const int* in_sizes, int n_in,
                              void* d_out, int out_size) {
    const float* x        = (const float*)d_in[0];
    const float* context  = (const float*)d_in[1];
    const float* A_logits = (const float*)d_in[2];
    const float* D_logits = (const float*)d_in[3];
    const float* mu       = (const float*)d_in[4];
    const float* log_var  = (const float*)d_in[5];
    const float* tA_w1 = (const float*)d_in[6];
    const float* tA_b1 = (const float*)d_in[7];
    const float* tA_w2 = (const float*)d_in[8];
    const float* tA_b2 = (const float*)d_in[9];
    const float* tD_w1 = (const float*)d_in[10];
    const float* tD_b1 = (const float*)d_in[11];
    const float* tD_w2 = (const float*)d_in[12];
    const float* tD_b2 = (const float*)d_in[13];
    const float* tE_w1 = (const float*)d_in[14];
    const float* tE_b1 = (const float*)d_in[15];
    const float* tE_w2 = (const float*)d_in[16];
    const float* tE_b2 = (const float*)d_in[17];
    float* out = (float*)d_out;

    k_layer1<<<1280, 256>>>(context, tA_w1, tA_b1, tD_w1, tD_b1, tE_w1, tE_b1);
    k_layer2<<<1280, 256>>>(tA_w2, tA_b2, tD_w2, tD_b2, tE_w2, tE_b2);
    k_params<<<1, 64>>>(A_logits, D_logits, mu, log_var);
    dim3 gB(TT / 16, BB);
    k_logB<<<gB, 1024>>>(x);
    k_recur<<<BB, 128>>>(out);
}

// round 3
// speedup vs baseline: 2.9073x; 2.9073x over previous
#include <cuda_runtime.h>
#include <math.h>

#define S    64
#define DMAX 32
#define TT   1024
#define BB   32
#define FF   64
#define CC   128
#define LOG2E 1.4426950408889634f
#define LN2   0.6931471805599453f
#define LOGPI2 (-6.0f)                 /* log2(1/64) */
#define LOG2PI 1.83787706640934534f

// ---------------- scratch ----------------
__device__ __align__(16) float g_h[10240];
__device__ __align__(16) float g_delta[10240];
__device__ __align__(16) float g_A[S * S];          // linear probs, [s_from][s_to]
__device__ __align__(16) float g_logDur2[DMAX * S]; // log2 domain, [d][s]
__device__ __align__(16) float g_dmax2[S];          // max_d(logDur2[d]-logDur2[d-1])
__device__ __align__(16) float g_coefAT[S * FF];    // f4-blocked: [(f>>2)*256 + s*4 + (f&3)]
__device__ __align__(16) float g_coefBT[S * FF];
__device__ __align__(16) float g_constS[S];
__device__ __align__(16) float g_logB2[(size_t)BB * TT * S];  // log2 domain
__device__ __align__(16) float g_bmax2[BB * TT];

__device__ __forceinline__ float ex2f(float x){ float y; asm("ex2.approx.ftz.f32 %0,%1;" : "=f"(y) : "f"(x)); return y; }
__device__ __forceinline__ float lg2f(float x){ float y; asm("lg2.approx.ftz.f32 %0,%1;" : "=f"(y) : "f"(x)); return y; }

// ---------------- kernel 1a: hidden = tanh(W1 @ ctx + b1), warp per row ----------------
__global__ void k_layer1(const float* __restrict__ ctx,
                         const float* __restrict__ wA, const float* __restrict__ bA,
                         const float* __restrict__ wD, const float* __restrict__ bD,
                         const float* __restrict__ wE, const float* __restrict__ bE) {
    int warp = (blockIdx.x * blockDim.x + threadIdx.x) >> 5;
    int lane = threadIdx.x & 31;
    if (warp >= 10240) return;
    const float* w; const float* bb; int r;
    if (warp < 4096)      { w = wA; bb = bA; r = warp; }
    else if (warp < 6144) { w = wD; bb = bD; r = warp - 4096; }
    else                  { w = wE; bb = bE; r = warp - 6144; }
    const float4* wr = (const float4*)(w + (size_t)r * CC);
    float4 wv = wr[lane];
    float4 cv = ((const float4*)ctx)[lane];
    float sum = wv.x * cv.x + wv.y * cv.y + wv.z * cv.z + wv.w * cv.w;
    #pragma unroll
    for (int o = 16; o; o >>= 1) sum += __shfl_xor_sync(0xffffffffu, sum, o);
    if (lane == 0) g_h[warp] = tanhf(sum + bb[r]);
}

// ---------------- kernel 1b: delta = W2 @ h + b2 ----------------
__global__ void k_layer2(const float* __restrict__ w2A, const float* __restrict__ b2A,
                         const float* __restrict__ w2D, const float* __restrict__ b2D,
                         const float* __restrict__ w2E, const float* __restrict__ b2E) {
    __shared__ __align__(16) float sh[4096];
    int rowBase = blockIdx.x * 8;
    const float* w2; const float* b2; int N, hoff, lr;
    if (rowBase < 4096)      { w2 = w2A; b2 = b2A; N = 4096; hoff = 0;    lr = rowBase; }
    else if (rowBase < 6144) { w2 = w2D; b2 = b2D; N = 2048; hoff = 4096; lr = rowBase - 4096; }
    else                     { w2 = w2E; b2 = b2E; N = 4096; hoff = 6144; lr = rowBase - 6144; }
    for (int i = threadIdx.x; i < N / 4; i += 256)
        ((float4*)sh)[i] = ((const float4*)(g_h + hoff))[i];
    __syncthreads();
    int wid = threadIdx.x >> 5, lane = threadIdx.x & 31;
    int r = lr + wid;
    const float4* wr = (const float4*)(w2 + (size_t)r * N);
    float sum = 0.f;
    for (int k4 = lane; k4 < N / 4; k4 += 32) {
        float4 wv = wr[k4];
        float4 hv = ((const float4*)sh)[k4];
        sum += wv.x * hv.x + wv.y * hv.y + wv.z * hv.z + wv.w * hv.w;
    }
    #pragma unroll
    for (int o = 16; o; o >>= 1) sum += __shfl_xor_sync(0xffffffffu, sum, o);
    if (lane == 0) g_delta[rowBase + wid] = sum + b2[r];
}

// ---------------- kernel 1c: derived parameters ----------------
__global__ void k_params(const float* __restrict__ A_logits, const float* __restrict__ D_logits,
                         const float* __restrict__ mu, const float* __restrict__ log_var) {
    int s = threadIdx.x;   // 64 threads
    const float* dA = g_delta;
    float m = -1e30f;
    for (int j = 0; j < S; j++)
        m = fmaxf(m, A_logits[s * S + j] + 0.1f * tanhf(dA[s * S + j]));
    float sum = 0.f;
    for (int j = 0; j < S; j++)
        sum += __expf(A_logits[s * S + j] + 0.1f * tanhf(dA[s * S + j]) - m);
    float inv = 1.f / sum;
    for (int j = 0; j < S; j++)
        g_A[s * S + j] = __expf(A_logits[s * S + j] + 0.1f * tanhf(dA[s * S + j]) - m) * inv;

    const float* dD = g_delta + 4096;
    float ld[DMAX];
    m = -1e30f;
    for (int d = 0; d < DMAX; d++) {
        ld[d] = D_logits[s * DMAX + d] + 0.1f * tanhf(dD[s * DMAX + d]);
        m = fmaxf(m, ld[d]);
    }
    sum = 0.f;
    for (int d = 0; d < DMAX; d++) sum += __expf(ld[d] - m);
    float lsum = __logf(sum);
    float dmx = -1e30f;
    for (int d = 0; d < DMAX; d++) {
        float v = (ld[d] - m - lsum) * LOG2E;
        g_logDur2[d * S + s] = v;
        if (d > 0) dmx = fmaxf(dmx, (ld[d] - ld[d - 1]) * LOG2E);
    }
    g_dmax2[s] = dmx;

    const float* dE = g_delta + 6144;
    float c = 0.f;
    for (int f = 0; f < FF; f++) {
        float mc = mu[s * FF + f] + 0.1f * tanhf(dE[s * FF + f]);
        float z  = log_var[s * FF + f];
        float sp = fmaxf(z, 0.f) + log1pf(__expf(-fabsf(z)));
        float var = sp + 0.001f;
        float iv = 1.f / var;
        int idx = (f >> 2) * 256 + s * 4 + (f & 3);
        g_coefAT[idx] = -0.5f * iv;
        g_coefBT[idx] = mc * iv;
        c += mc * mc * iv + __logf(var);
    }
    g_constS[s] = -0.5f * (c + (float)FF * LOG2PI);
}

// ---------------- kernel 2: logB2[b][t][s], 8 t's per thread ----------------
__global__ void __launch_bounds__(256) k_logB(const float* __restrict__ x) {
    __shared__ __align__(16) float scA[S * FF];
    __shared__ __align__(16) float scB[S * FF];
    __shared__ float scs[S];
    int tid = threadIdx.x;
    for (int i = tid; i < S * FF / 4; i += 256) {
        ((float4*)scA)[i] = ((const float4*)g_coefAT)[i];
        ((float4*)scB)[i] = ((const float4*)g_coefBT)[i];
    }
    if (tid < S) scs[tid] = g_constS[tid];
    __syncthreads();
    int s = tid & 63, q = tid >> 6;
    int b = blockIdx.y;
    int t0 = blockIdx.x * 32 + q * 8;
    const float4* xp = (const float4*)(x + ((size_t)b * TT + t0) * FF);
    float acc[8];
    #pragma unroll
    for (int i = 0; i < 8; i++) acc[i] = scs[s];
    #pragma unroll
    for (int f4 = 0; f4 < 16; f4++) {
        float4 ca = ((const float4*)scA)[f4 * 64 + s];
        float4 cb = ((const float4*)scB)[f4 * 64 + s];
        #pragma unroll
        for (int i = 0; i < 8; i++) {
            float4 xv = xp[i * 16 + f4];
            acc[i] = fmaf(xv.x, fmaf(ca.x, xv.x, cb.x), acc[i]);
            acc[i] = fmaf(xv.y, fmaf(ca.y, xv.y, cb.y), acc[i]);
            acc[i] = fmaf(xv.z, fmaf(ca.z, xv.z, cb.z), acc[i]);
            acc[i] = fmaf(xv.w, fmaf(ca.w, xv.w, cb.w), acc[i]);
        }
    }
    float* op = g_logB2 + ((size_t)b * TT + t0) * S + s;
    #pragma unroll
    for (int i = 0; i < 8; i++) op[i * S] = acc[i] * LOG2E;
}

// ---------------- kernel 2b: per-(b,t) max over s of logB2 ----------------
__global__ void k_bmax() {
    int lane = threadIdx.x & 31;
    int row = blockIdx.x * 8 + (threadIdx.x >> 5);
    if (row >= BB * TT) return;
    const float* p = g_logB2 + (size_t)row * S;
    float v = fmaxf(p[lane], p[lane + 32]);
    #pragma unroll
    for (int o = 16; o; o >>= 1) v = fmaxf(v, __shfl_xor_sync(0xffffffffu, v, o));
    if (lane == 0) g_bmax2[row] = v;
}

// ---------------- kernel 3: sequential HSMM forward, one block per batch ----------------
// log2 domain throughout. 3 barriers/step. No reductions on the critical path:
//  - per-state stage-1 normalizer m1[s] from the exact shift identity
//    alpha_t[s] <= max(trans_{t-1}[s]+logDur[1][s], alpha_{t-1}[s]+dmax[s]) + logB_t[s] + 1 (log2)
//  - global normalizer N_t = M_{t-1} + bmax_t, M via REDUX one step late (off chain).
__global__ void __launch_bounds__(128, 1) k_recur(float* __restrict__ out) {
    __shared__ float sTr[64 * S];    // trans ring (32 slots), mirrored at +32
    __shared__ float sCc[66 * S];    // Ccum ring (33 slots), mirrored at +33
    __shared__ float sPs[2][S];
    __shared__ float sE[S];
    __shared__ float sDot[2][S];
    __shared__ unsigned sMk[2];
    __shared__ float sBm[TT];
    int tid = threadIdx.x;
    int s = tid & 63, g = tid >> 6;
    int lane = tid & 31, wid = tid >> 5;
    int b = blockIdx.x;

    float rLD[16], rA[32];
    #pragma unroll
    for (int i = 0; i < 16; i++) rLD[i] = g_logDur2[(g * 16 + i) * S + s];
    #pragma unroll
    for (int j = 0; j < 32; j++) rA[j] = g_A[(g * 32 + j) * S + s];
    float rLDd1 = g_logDur2[0 * S + s];        // logDur2[d=1][s], all threads
    float rDmax = g_dmax2[s];
    for (int i = tid; i < TT; i += 128) sBm[i] = g_bmax2[b * TT + i];

    const float* lbp = g_logB2 + (size_t)b * TT * S + s;
    float lb = lbp[0];
    float ccum = 0.f;
    if (g == 0) sCc[0 * S + s] = 0.f; else sCc[33 * S + s] = 0.f;   // Ccum[0]
    __syncthreads();

    float Nt = LOGPI2 + sBm[0];
    float alphaP = 0.f;
    int cur = 1;                        // slot of Ccum[t+1]

    for (int t = 0; t < TT; t++) {
        // ---------- P0: trans_{t-1} from prev dot partials; N_t update; Ccum append ----------
        float trNew = 0.f;
        if (t > 0) {
            trNew = Nt + lg2f(sDot[0][s] + sDot[1][s]);     // uses N_{t-1}
            int w = (t - 1) & 31;
            if (g == 0) sTr[(w + 32) * S + s] = trNew; else sTr[w * S + s] = trNew;
            float mprev = fmaxf(__uint_as_float(sMk[0]), __uint_as_float(sMk[1]));
            Nt = (Nt + lg2f(mprev)) + sBm[t];               // M_{t-1} + bmax_t
        }
        ccum += lb;                                          // Ccum[t+1]
        if (g == 0) sCc[cur * S + s] = ccum; else sCc[(cur + 33) * S + s] = ccum;
        float lbN = (t + 1 < TT) ? lbp[(size_t)(t + 1) * S] : 0.f;   // prefetch

        // ---------- stage 1: duration-lse partial sums ----------
        float m1 = (t == 0) ? (LOGPI2 + rLDd1 + ccum)
                            : (fmaxf(trNew + rLDd1, alphaP + rDmax) + lb + 1.0f);
        float base = ccum - m1;
        float sum = 0.f;
        if (t >= 32) {
            const float* trB = sTr + (((t - 1) & 31) + 32 - g * 16) * S + s;
            const float* ccB = sCc + (cur + 33 - g * 16) * S + s;
            #pragma unroll
            for (int i = 0; i < 16; i++) {
                float tr = (g == 0 && i == 0) ? trNew : trB[-i * S];
                sum += ex2f(tr + rLD[i] + (base - ccB[-(i + 1) * S]));
            }
        } else {
            #pragma unroll
            for (int i = 0; i < 16; i++) {
                int d = g * 16 + i + 1;
                if (d <= t) {
                    float tr = (g == 0 && i == 0) ? trNew : sTr[(((t - d) & 31) + 32) * S + s];
                    sum += ex2f(tr + rLD[i] + (base - sCc[(cur + 33 - d) * S + s]));
                } else if (d == t + 1) {
                    sum += ex2f(LOGPI2 + rLD[i] + base);     // Ccum[0]=0
                }
            }
        }
        sPs[g][s] = sum;
        __syncthreads();                                     // B1

        // ---------- stage 2: alpha, e, off-chain max key ----------
        float alpha = m1 + lg2f(sPs[0][s] + sPs[1][s]);
        float e = ex2f(alpha - Nt);
        if (g == 0) {
            sE[s] = e;
            unsigned k = __reduce_max_sync(0xffffffffu, __float_as_uint(e));
            if (lane == 0) sMk[wid] = k;
        }
        alphaP = alpha;
        __syncthreads();                                     // B2

        // ---------- stage 3: dot partials e . A ----------
        float acc = 0.f;
        #pragma unroll
        for (int j = 0; j < 32; j++) acc = fmaf(sE[g * 32 + j], rA[j], acc);
        sDot[g][s] = acc;
        __syncthreads();                                     // B3

        cur++; if (cur == 33) cur = 0;
        lb = lbN;
    }
    if (tid == 0) {
        float ssum = 0.f;
        for (int j = 0; j < S; j++) ssum += sE[j];
        out[b] = (Nt + lg2f(ssum)) * LN2;
    }
}

// ---------------- launch ----------------
extern "C" void kernel_launch(void* const* d_in, const int* in_sizes, int n_in,
                              void* d_out, int out_size) {
    const float* x        = (const float*)d_in[0];
    const float* context  = (const float*)d_in[1];
    const float* A_logits = (const float*)d_in[2];
    const float* D_logits = (const float*)d_in[3];
    const float* mu       = (const float*)d_in[4];
    const float* log_var  = (const float*)d_in[5];
    const float* tA_w1 = (const float*)d_in[6];
    const float* tA_b1 = (const float*)d_in[7];
    const float* tA_w2 = (const float*)d_in[8];
    const float* tA_b2 = (const float*)d_in[9];
    const float* tD_w1 = (const float*)d_in[10];
    const float* tD_b1 = (const float*)d_in[11];
    const float* tD_w2 = (const float*)d_in[12];
    const float* tD_b2 = (const float*)d_in[13];
    const float* tE_w1 = (const float*)d_in[14];
    const float* tE_b1 = (const float*)d_in[15];
    const float* tE_w2 = (const float*)d_in[16];
    const float* tE_b2 = (const float*)d_in[17];
    float* out = (float*)d_out;

    k_layer1<<<1280, 256>>>(context, tA_w1, tA_b1, tD_w1, tD_b1, tE_w1, tE_b1);
    k_layer2<<<1280, 256>>>(tA_w2, tA_b2, tD_w2, tD_b2, tE_w2, tE_b2);
    k_params<<<1, 64>>>(A_logits, D_logits, mu, log_var);
    dim3 gB(TT / 32, BB);
    k_logB<<<gB, 256>>>(x);
    k_bmax<<<(BB * TT + 7) / 8, 256>>>();
    k_recur<<<BB, 128>>>(out);
}

// round 4
// speedup vs baseline: 4.9847x; 1.7146x over previous
#include <cuda_runtime.h>
#include <math.h>

#define S    64
#define DMAX 32
#define TT   1024
#define BB   32
#define FF   64
#define CC   128
#define LOG2E 1.4426950408889634f
#define LN2   0.6931471805599453f
#define LOGPI2 (-6.0f)                 /* log2(1/64) */
#define LOG2PI 1.83787706640934534f

// ---------------- scratch ----------------
__device__ __align__(16) float g_h[10240];
__device__ __align__(16) float g_delta[10240];
__device__ __align__(16) float g_A[S * S];          // linear probs, [s_from][s_to]
__device__ __align__(16) float g_logDur2[DMAX * S]; // log2 domain, [d][s]
__device__ __align__(16) float g_dmax2[S];          // max_d(logDur2[d]-logDur2[d-1])
__device__ __align__(16) float g_coefAT[S * FF];    // f4-blocked
__device__ __align__(16) float g_coefBT[S * FF];
__device__ __align__(16) float g_constS[S];
__device__ __align__(16) float g_logB2[(size_t)BB * TT * S];  // log2 domain
__device__ __align__(16) float g_bmax2[BB * TT];

__device__ __forceinline__ float ex2f(float x){ float y; asm("ex2.approx.ftz.f32 %0,%1;" : "=f"(y) : "f"(x)); return y; }
__device__ __forceinline__ float lg2f(float x){ float y; asm("lg2.approx.ftz.f32 %0,%1;" : "=f"(y) : "f"(x)); return y; }

// ---------------- kernel 1a: hidden = tanh(W1 @ ctx + b1) ----------------
__global__ void k_layer1(const float* __restrict__ ctx,
                         const float* __restrict__ wA, const float* __restrict__ bA,
                         const float* __restrict__ wD, const float* __restrict__ bD,
                         const float* __restrict__ wE, const float* __restrict__ bE) {
    int warp = (blockIdx.x * blockDim.x + threadIdx.x) >> 5;
    int lane = threadIdx.x & 31;
    if (warp >= 10240) return;
    const float* w; const float* bb; int r;
    if (warp < 4096)      { w = wA; bb = bA; r = warp; }
    else if (warp < 6144) { w = wD; bb = bD; r = warp - 4096; }
    else                  { w = wE; bb = bE; r = warp - 6144; }
    const float4* wr = (const float4*)(w + (size_t)r * CC);
    float4 wv = wr[lane];
    float4 cv = ((const float4*)ctx)[lane];
    float sum = wv.x * cv.x + wv.y * cv.y + wv.z * cv.z + wv.w * cv.w;
    #pragma unroll
    for (int o = 16; o; o >>= 1) sum += __shfl_xor_sync(0xffffffffu, sum, o);
    if (lane == 0) g_h[warp] = tanhf(sum + bb[r]);
}

// ---------------- kernel 1b: delta = W2 @ h + b2 ----------------
__global__ void k_layer2(const float* __restrict__ w2A, const float* __restrict__ b2A,
                         const float* __restrict__ w2D, const float* __restrict__ b2D,
                         const float* __restrict__ w2E, const float* __restrict__ b2E) {
    __shared__ __align__(16) float sh[4096];
    int rowBase = blockIdx.x * 8;
    const float* w2; const float* b2; int N, hoff, lr;
    if (rowBase < 4096)      { w2 = w2A; b2 = b2A; N = 4096; hoff = 0;    lr = rowBase; }
    else if (rowBase < 6144) { w2 = w2D; b2 = b2D; N = 2048; hoff = 4096; lr = rowBase - 4096; }
    else                     { w2 = w2E; b2 = b2E; N = 4096; hoff = 6144; lr = rowBase - 6144; }
    for (int i = threadIdx.x; i < N / 4; i += 256)
        ((float4*)sh)[i] = ((const float4*)(g_h + hoff))[i];
    __syncthreads();
    int wid = threadIdx.x >> 5, lane = threadIdx.x & 31;
    int r = lr + wid;
    const float4* wr = (const float4*)(w2 + (size_t)r * N);
    float sum = 0.f;
    for (int k4 = lane; k4 < N / 4; k4 += 32) {
        float4 wv = wr[k4];
        float4 hv = ((const float4*)sh)[k4];
        sum += wv.x * hv.x + wv.y * hv.y + wv.z * hv.z + wv.w * hv.w;
    }
    #pragma unroll
    for (int o = 16; o; o >>= 1) sum += __shfl_xor_sync(0xffffffffu, sum, o);
    if (lane == 0) g_delta[rowBase + wid] = sum + b2[r];
}

// ---------------- kernel 1c: derived parameters ----------------
__global__ void k_params(const float* __restrict__ A_logits, const float* __restrict__ D_logits,
                         const float* __restrict__ mu, const float* __restrict__ log_var) {
    int s = threadIdx.x;   // 64 threads
    const float* dA = g_delta;
    float m = -1e30f;
    for (int j = 0; j < S; j++)
        m = fmaxf(m, A_logits[s * S + j] + 0.1f * tanhf(dA[s * S + j]));
    float sum = 0.f;
    for (int j = 0; j < S; j++)
        sum += __expf(A_logits[s * S + j] + 0.1f * tanhf(dA[s * S + j]) - m);
    float inv = 1.f / sum;
    for (int j = 0; j < S; j++)
        g_A[s * S + j] = __expf(A_logits[s * S + j] + 0.1f * tanhf(dA[s * S + j]) - m) * inv;

    const float* dD = g_delta + 4096;
    float ld[DMAX];
    m = -1e30f;
    for (int d = 0; d < DMAX; d++) {
        ld[d] = D_logits[s * DMAX + d] + 0.1f * tanhf(dD[s * DMAX + d]);
        m = fmaxf(m, ld[d]);
    }
    sum = 0.f;
    for (int d = 0; d < DMAX; d++) sum += __expf(ld[d] - m);
    float lsum = __logf(sum);
    float dmx = -1e30f;
    for (int d = 0; d < DMAX; d++) {
        g_logDur2[d * S + s] = (ld[d] - m - lsum) * LOG2E;
        if (d > 0) dmx = fmaxf(dmx, (ld[d] - ld[d - 1]) * LOG2E);
    }
    g_dmax2[s] = dmx;

    const float* dE = g_delta + 6144;
    float c = 0.f;
    for (int f = 0; f < FF; f++) {
        float mc = mu[s * FF + f] + 0.1f * tanhf(dE[s * FF + f]);
        float z  = log_var[s * FF + f];
        float sp = fmaxf(z, 0.f) + log1pf(__expf(-fabsf(z)));
        float var = sp + 0.001f;
        float iv = 1.f / var;
        int idx = (f >> 2) * 256 + s * 4 + (f & 3);
        g_coefAT[idx] = -0.5f * iv;
        g_coefBT[idx] = mc * iv;
        c += mc * mc * iv + __logf(var);
    }
    g_constS[s] = -0.5f * (c + (float)FF * LOG2PI);
}

// ---------------- kernel 2: logB2[b][t][s], 8 t's per thread ----------------
__global__ void __launch_bounds__(256) k_logB(const float* __restrict__ x) {
    __shared__ __align__(16) float scA[S * FF];
    __shared__ __align__(16) float scB[S * FF];
    __shared__ float scs[S];
    int tid = threadIdx.x;
    for (int i = tid; i < S * FF / 4; i += 256) {
        ((float4*)scA)[i] = ((const float4*)g_coefAT)[i];
        ((float4*)scB)[i] = ((const float4*)g_coefBT)[i];
    }
    if (tid < S) scs[tid] = g_constS[tid];
    __syncthreads();
    int s = tid & 63, q = tid >> 6;
    int b = blockIdx.y;
    int t0 = blockIdx.x * 32 + q * 8;
    const float4* xp = (const float4*)(x + ((size_t)b * TT + t0) * FF);
    float acc[8];
    #pragma unroll
    for (int i = 0; i < 8; i++) acc[i] = scs[s];
    #pragma unroll
    for (int f4 = 0; f4 < 16; f4++) {
        float4 ca = ((const float4*)scA)[f4 * 64 + s];
        float4 cb = ((const float4*)scB)[f4 * 64 + s];
        #pragma unroll
        for (int i = 0; i < 8; i++) {
            float4 xv = xp[i * 16 + f4];
            acc[i] = fmaf(xv.x, fmaf(ca.x, xv.x, cb.x), acc[i]);
            acc[i] = fmaf(xv.y, fmaf(ca.y, xv.y, cb.y), acc[i]);
            acc[i] = fmaf(xv.z, fmaf(ca.z, xv.z, cb.z), acc[i]);
            acc[i] = fmaf(xv.w, fmaf(ca.w, xv.w, cb.w), acc[i]);
        }
    }
    float* op = g_logB2 + ((size_t)b * TT + t0) * S + s;
    #pragma unroll
    for (int i = 0; i < 8; i++) op[i * S] = acc[i] * LOG2E;
}

// ---------------- kernel 2b: per-(b,t) max over s of logB2 ----------------
__global__ void k_bmax() {
    int lane = threadIdx.x & 31;
    int row = blockIdx.x * 8 + (threadIdx.x >> 5);
    if (row >= BB * TT) return;
    const float* p = g_logB2 + (size_t)row * S;
    float v = fmaxf(p[lane], p[lane + 32]);
    #pragma unroll
    for (int o = 16; o; o >>= 1) v = fmaxf(v, __shfl_xor_sync(0xffffffffu, v, o));
    if (lane == 0) g_bmax2[row] = v;
}

// ---------------- kernel 3: HSMM forward; pre-exponentiated register window ----------------
// Window identity: alpha_t = Cc[t+1] + log2( sum_d exp2(q_{t-d}) * eLD_d ), q_j = tr_j - Cc[j+1].
// Ring W holds exp2(q_j - R_t), R_t = m1_t - Cc[t+1] (R3's proven surrogate normalizer),
// rescaled by f = 2^{-(m1_t - m1_{t-1} - lb_t)} each step. Init-pi term is a seeded ring entry.
// Lane layout: warp w covers s in [16w,16w+16); lane = 2*(s&15)+g; pair combine via shfl_xor(1).
// ONE __syncthreads per step (double-buffered sE / sMk).
__global__ void __launch_bounds__(128, 1) k_recur(float* __restrict__ out) {
    __shared__ __align__(16) float sE[2][S];
    __shared__ float sMk[2][4];
    __shared__ float sBm[TT];
    int tid = threadIdx.x;
    int lane = tid & 31, w = tid >> 5;
    int g = lane & 1;
    int s = w * 16 + (lane >> 1);
    int b = blockIdx.x;

    float eLD[16], rA[32];
    #pragma unroll
    for (int i = 0; i < 16; i++) eLD[i] = ex2f(g_logDur2[(g * 16 + i) * S + s]);
    #pragma unroll
    for (int j = 0; j < 32; j++) rA[j] = g_A[(g * 32 + j) * S + s];
    float LD1  = g_logDur2[0 * S + s];
    float dmax = g_dmax2[s];
    for (int i = tid; i < TT; i += 128) sBm[i] = g_bmax2[b * TT + i];

    const float* lbp = g_logB2 + (size_t)b * TT * S + s;
    float lb  = lbp[0];
    float lb1 = lbp[S];

    float W[16];
    #pragma unroll
    for (int i = 0; i < 16; i++) W[i] = 0.f;

    float Nt = 0.f, m1P = 0.f, alphaP = 0.f, eFin = 0.f;
    __syncthreads();

    for (int tb = 0; tb < TT; tb += 16) {
        #pragma unroll
        for (int p = 0; p < 16; p++) {
            int t = tb + p;
            int par = t & 1, parP = par ^ 1;
            float lb2 = (t + 2 < TT) ? lbp[(size_t)(t + 2) * S] : 0.f;  // distance-2 prefetch

            float m1, f, wnew;
            if (t == 0) {
                m1 = LOGPI2 + LD1 + lb;
                Nt = LOGPI2 + sBm[0];
                f  = 1.0f;
                wnew = ex2f(LOGPI2 + lb - m1);          // = 2^{-LD1}
            } else {
                // trans_{t-1}: dot e_{t-1} . A over this thread's s'-half, pair-combined
                const float4* ep = (const float4*)(sE[parP] + g * 32);
                float a0 = 0.f, a1 = 0.f, a2 = 0.f, a3 = 0.f;
                #pragma unroll
                for (int j4 = 0; j4 < 8; j4++) {
                    float4 ev = ep[j4];
                    a0 = fmaf(ev.x, rA[j4 * 4 + 0], a0);
                    a1 = fmaf(ev.y, rA[j4 * 4 + 1], a1);
                    a2 = fmaf(ev.z, rA[j4 * 4 + 2], a2);
                    a3 = fmaf(ev.w, rA[j4 * 4 + 3], a3);
                }
                float etr = (a0 + a1) + (a2 + a3);
                etr += __shfl_xor_sync(0xffffffffu, etr, 1);
                float NtP = Nt;
                float trLog = NtP + lg2f(etr);
                float mp = fmaxf(fmaxf(sMk[parP][0], sMk[parP][1]),
                                 fmaxf(sMk[parP][2], sMk[parP][3]));
                Nt = NtP + lg2f(mp) + sBm[t];           // = max alpha_{t-1} + bmax_t
                m1 = fmaxf(trLog + LD1, alphaP + dmax) + lb + 1.0f;
                f    = ex2f(m1P + lb - m1);             // ring rescale 2^{-delta}
                wnew = etr * ex2f(NtP + lb - m1);       // exp2(tr_{t-1}+lb_t-m1_t)
            }

            // ring shift (static rotation p), rescale, insert, dot
            float outv = W[p & 15];                      // leaving entry (label 15)
            float inv_ = __shfl_xor_sync(0xffffffffu, outv, 1);
            float d0 = 0.f, d1 = 0.f, d2 = 0.f, d3 = 0.f;
            #pragma unroll
            for (int r = 0; r < 16; r++) {
                float val = (r == (p & 15)) ? ((g == 0) ? wnew : inv_ * f)
                                            : W[r] * f;
                W[r] = val;
                int i = (r - p) & 15;                    // duration label (static)
                if ((r & 3) == 0)      d0 = fmaf(val, eLD[i], d0);
                else if ((r & 3) == 1) d1 = fmaf(val, eLD[i], d1);
                else if ((r & 3) == 2) d2 = fmaf(val, eLD[i], d2);
                else                   d3 = fmaf(val, eLD[i], d3);
            }
            float dsum = (d0 + d1) + (d2 + d3);
            float dfull = dsum + __shfl_xor_sync(0xffffffffu, dsum, 1);

            float alpha = m1 + lg2f(dfull);
            float e = dfull * ex2f(m1 - Nt);
            if (g == 0) sE[par][s] = e;
            unsigned k = __reduce_max_sync(0xffffffffu, __float_as_uint(e));
            if (lane == 0) sMk[par][w] = __uint_as_float(k);
            alphaP = alpha; m1P = m1;
            lb = lb1; lb1 = lb2;
            eFin = e;
            __syncthreads();
        }
    }
    (void)eFin;
    if (tid == 0) {
        float ssum = 0.f;
        for (int j = 0; j < S; j++) ssum += sE[(TT - 1) & 1][j];
        out[b] = (Nt + lg2f(ssum)) * LN2;
    }
}

// ---------------- launch ----------------
extern "C" void kernel_launch(void* const* d_in, const int* in_sizes, int n_in,
                              void* d_out, int out_size) {
    const float* x        = (const float*)d_in[0];
    const float* context  = (const float*)d_in[1];
    const float* A_logits = (const float*)d_in[2];
    const float* D_logits = (const float*)d_in[3];
    const float* mu       = (const float*)d_in[4];
    const float* log_var  = (const float*)d_in[5];
    const float* tA_w1 = (const float*)d_in[6];
    const float* tA_b1 = (const float*)d_in[7];
    const float* tA_w2 = (const float*)d_in[8];
    const float* tA_b2 = (const float*)d_in[9];
    const float* tD_w1 = (const float*)d_in[10];
    const float* tD_b1 = (const float*)d_in[11];
    const float* tD_w2 = (const float*)d_in[12];
    const float* tD_b2 = (const float*)d_in[13];
    const float* tE_w1 = (const float*)d_in[14];
    const float* tE_b1 = (const float*)d_in[15];
    const float* tE_w2 = (const float*)d_in[16];
    const float* tE_b2 = (const float*)d_in[17];
    float* out = (float*)d_out;

    k_layer1<<<1280, 256>>>(context, tA_w1, tA_b1, tD_w1, tD_b1, tE_w1, tE_b1);
    k_layer2<<<1280, 256>>>(tA_w2, tA_b2, tD_w2, tD_b2, tE_w2, tE_b2);
    k_params<<<1, 64>>>(A_logits, D_logits, mu, log_var);
    dim3 gB(TT / 32, BB);
    k_logB<<<gB, 256>>>(x);
    k_bmax<<<(BB * TT + 7) / 8, 256>>>();
    k_recur<<<BB, 128>>>(out);
}

// round 5
// speedup vs baseline: 5.5919x; 1.1218x over previous
#include <cuda_runtime.h>
#include <math.h>

#define S    64
#define DMAX 32
#define TT   1024
#define BB   32
#define FF   64
#define CC   128
#define LOG2E 1.4426950408889634f
#define LN2   0.6931471805599453f
#define LOGPI2 (-6.0f)                 /* log2(1/64) */
#define LOG2PI 1.83787706640934534f

// ---------------- scratch ----------------
__device__ __align__(16) float g_h[10240];
__device__ __align__(16) float g_delta[10240];
__device__ __align__(16) float g_A[S * S];          // linear probs, [s_from][s_to]
__device__ __align__(16) float g_logDur2[DMAX * S]; // log2 domain, [d][s]
__device__ __align__(16) float g_mdj[S];            // fmax(LD1, dmax) + 1
__device__ __align__(16) float g_coefAT[S * FF];    // f4-blocked
__device__ __align__(16) float g_coefBT[S * FF];
__device__ __align__(16) float g_constS[S];
__device__ __align__(16) float g_logB2[(size_t)BB * TT * S];  // log2 domain
__device__ __align__(16) float g_bmax2[BB * TT];

__device__ __forceinline__ float ex2f(float x){ float y; asm("ex2.approx.ftz.f32 %0,%1;" : "=f"(y) : "f"(x)); return y; }
__device__ __forceinline__ float lg2f(float x){ float y; asm("lg2.approx.ftz.f32 %0,%1;" : "=f"(y) : "f"(x)); return y; }

// ---------------- kernel 1a: hidden = tanh(W1 @ ctx + b1) ----------------
__global__ void k_layer1(const float* __restrict__ ctx,
                         const float* __restrict__ wA, const float* __restrict__ bA,
                         const float* __restrict__ wD, const float* __restrict__ bD,
                         const float* __restrict__ wE, const float* __restrict__ bE) {
    int warp = (blockIdx.x * blockDim.x + threadIdx.x) >> 5;
    int lane = threadIdx.x & 31;
    if (warp >= 10240) return;
    const float* w; const float* bb; int r;
    if (warp < 4096)      { w = wA; bb = bA; r = warp; }
    else if (warp < 6144) { w = wD; bb = bD; r = warp - 4096; }
    else                  { w = wE; bb = bE; r = warp - 6144; }
    const float4* wr = (const float4*)(w + (size_t)r * CC);
    float4 wv = wr[lane];
    float4 cv = ((const float4*)ctx)[lane];
    float sum = wv.x * cv.x + wv.y * cv.y + wv.z * cv.z + wv.w * cv.w;
    #pragma unroll
    for (int o = 16; o; o >>= 1) sum += __shfl_xor_sync(0xffffffffu, sum, o);
    if (lane == 0) g_h[warp] = tanhf(sum + bb[r]);
}

// ---------------- kernel 1b: delta = W2 @ h + b2 ----------------
__global__ void k_layer2(const float* __restrict__ w2A, const float* __restrict__ b2A,
                         const float* __restrict__ w2D, const float* __restrict__ b2D,
                         const float* __restrict__ w2E, const float* __restrict__ b2E) {
    __shared__ __align__(16) float sh[4096];
    int rowBase = blockIdx.x * 8;
    const float* w2; const float* b2; int N, hoff, lr;
    if (rowBase < 4096)      { w2 = w2A; b2 = b2A; N = 4096; hoff = 0;    lr = rowBase; }
    else if (rowBase < 6144) { w2 = w2D; b2 = b2D; N = 2048; hoff = 4096; lr = rowBase - 4096; }
    else                     { w2 = w2E; b2 = b2E; N = 4096; hoff = 6144; lr = rowBase - 6144; }
    for (int i = threadIdx.x; i < N / 4; i += 256)
        ((float4*)sh)[i] = ((const float4*)(g_h + hoff))[i];
    __syncthreads();
    int wid = threadIdx.x >> 5, lane = threadIdx.x & 31;
    int r = lr + wid;
    const float4* wr = (const float4*)(w2 + (size_t)r * N);
    float sum = 0.f;
    for (int k4 = lane; k4 < N / 4; k4 += 32) {
        float4 wv = wr[k4];
        float4 hv = ((const float4*)sh)[k4];
        sum += wv.x * hv.x + wv.y * hv.y + wv.z * hv.z + wv.w * hv.w;
    }
    #pragma unroll
    for (int o = 16; o; o >>= 1) sum += __shfl_xor_sync(0xffffffffu, sum, o);
    if (lane == 0) g_delta[rowBase + wid] = sum + b2[r];
}

// ---------------- kernel 1c: derived parameters ----------------
__global__ void k_params(const float* __restrict__ A_logits, const float* __restrict__ D_logits,
                         const float* __restrict__ mu, const float* __restrict__ log_var) {
    int s = threadIdx.x;   // 64 threads
    const float* dA = g_delta;
    float m = -1e30f;
    for (int j = 0; j < S; j++)
        m = fmaxf(m, A_logits[s * S + j] + 0.1f * tanhf(dA[s * S + j]));
    float sum = 0.f;
    for (int j = 0; j < S; j++)
        sum += __expf(A_logits[s * S + j] + 0.1f * tanhf(dA[s * S + j]) - m);
    float inv = 1.f / sum;
    for (int j = 0; j < S; j++)
        g_A[s * S + j] = __expf(A_logits[s * S + j] + 0.1f * tanhf(dA[s * S + j]) - m) * inv;

    const float* dD = g_delta + 4096;
    float ld[DMAX];
    m = -1e30f;
    for (int d = 0; d < DMAX; d++) {
        ld[d] = D_logits[s * DMAX + d] + 0.1f * tanhf(dD[s * DMAX + d]);
        m = fmaxf(m, ld[d]);
    }
    sum = 0.f;
    for (int d = 0; d < DMAX; d++) sum += __expf(ld[d] - m);
    float lsum = __logf(sum);
    float dmx = -1e30f;
    for (int d = 0; d < DMAX; d++) {
        g_logDur2[d * S + s] = (ld[d] - m - lsum) * LOG2E;
        if (d > 0) dmx = fmaxf(dmx, (ld[d] - ld[d - 1]) * LOG2E);
    }
    g_mdj[s] = fmaxf((ld[0] - m - lsum) * LOG2E, dmx) + 1.0f;

    const float* dE = g_delta + 6144;
    float c = 0.f;
    for (int f = 0; f < FF; f++) {
        float mc = mu[s * FF + f] + 0.1f * tanhf(dE[s * FF + f]);
        float z  = log_var[s * FF + f];
        float sp = fmaxf(z, 0.f) + log1pf(__expf(-fabsf(z)));
        float var = sp + 0.001f;
        float iv = 1.f / var;
        int idx = (f >> 2) * 256 + s * 4 + (f & 3);
        g_coefAT[idx] = -0.5f * iv;
        g_coefBT[idx] = mc * iv;
        c += mc * mc * iv + __logf(var);
    }
    g_constS[s] = -0.5f * (c + (float)FF * LOG2PI);
}

// ---------------- kernel 2: logB2[b][t][s], 8 t's per thread ----------------
__global__ void __launch_bounds__(256) k_logB(const float* __restrict__ x) {
    __shared__ __align__(16) float scA[S * FF];
    __shared__ __align__(16) float scB[S * FF];
    __shared__ float scs[S];
    int tid = threadIdx.x;
    for (int i = tid; i < S * FF / 4; i += 256) {
        ((float4*)scA)[i] = ((const float4*)g_coefAT)[i];
        ((float4*)scB)[i] = ((const float4*)g_coefBT)[i];
    }
    if (tid < S) scs[tid] = g_constS[tid];
    __syncthreads();
    int s = tid & 63, q = tid >> 6;
    int b = blockIdx.y;
    int t0 = blockIdx.x * 32 + q * 8;
    const float4* xp = (const float4*)(x + ((size_t)b * TT + t0) * FF);
    float acc[8];
    #pragma unroll
    for (int i = 0; i < 8; i++) acc[i] = scs[s];
    #pragma unroll
    for (int f4 = 0; f4 < 16; f4++) {
        float4 ca = ((const float4*)scA)[f4 * 64 + s];
        float4 cb = ((const float4*)scB)[f4 * 64 + s];
        #pragma unroll
        for (int i = 0; i < 8; i++) {
            float4 xv = xp[i * 16 + f4];
            acc[i] = fmaf(xv.x, fmaf(ca.x, xv.x, cb.x), acc[i]);
            acc[i] = fmaf(xv.y, fmaf(ca.y, xv.y, cb.y), acc[i]);
            acc[i] = fmaf(xv.z, fmaf(ca.z, xv.z, cb.z), acc[i]);
            acc[i] = fmaf(xv.w, fmaf(ca.w, xv.w, cb.w), acc[i]);
        }
    }
    float* op = g_logB2 + ((size_t)b * TT + t0) * S + s;
    #pragma unroll
    for (int i = 0; i < 8; i++) op[i * S] = acc[i] * LOG2E;
}

// ---------------- kernel 2b: per-(b,t) max over s of logB2 ----------------
__global__ void k_bmax() {
    int lane = threadIdx.x & 31;
    int row = blockIdx.x * 8 + (threadIdx.x >> 5);
    if (row >= BB * TT) return;
    const float* p = g_logB2 + (size_t)row * S;
    float v = fmaxf(p[lane], p[lane + 32]);
    #pragma unroll
    for (int o = 16; o; o >>= 1) v = fmaxf(v, __shfl_xor_sync(0xffffffffu, v, o));
    if (lane == 0) g_bmax2[row] = v;
}

// ---------------- kernel 3: HSMM forward; MUFU-free critical chain ----------------
// m1_t = MA_{t-1} + max(LD1,dmax)[s] + lb_t[s] + 1, MA = Nt + lg2(mp) (exact max alpha_{t-1}
// from previous step's REDUX). All ex2/lg2 run parallel to the e.A dot; the e->e chain is
// LDS -> 32FMA dot -> shfl -> 2 FMA (f*D2 + new*eLD0, D2 pipelined from prev step) -> shfl
// -> MUL -> STS. One barrier/step, double-buffered sE/sMk.
__global__ void __launch_bounds__(128, 1) k_recur(float* __restrict__ out) {
    __shared__ __align__(16) float sE[2][S];
    __shared__ float sMk[2][4];
    __shared__ float sBm[TT];
    int tid = threadIdx.x;
    int lane = tid & 31, w = tid >> 5;
    int g = lane & 1;
    int s = w * 16 + (lane >> 1);
    int b = blockIdx.x;

    float eLD[16], rA[32];
    #pragma unroll
    for (int i = 0; i < 16; i++) eLD[i] = ex2f(g_logDur2[(g * 16 + i) * S + s]);
    #pragma unroll
    for (int j = 0; j < 32; j++) rA[j] = g_A[(g * 32 + j) * S + s];
    float LD1 = g_logDur2[0 * S + s];
    float mdj = g_mdj[s];
    for (int i = tid; i < TT; i += 128) sBm[i] = g_bmax2[b * TT + i];

    const float* lbp = g_logB2 + (size_t)b * TT * S + s;
    float lb  = lbp[0];
    float lb1 = lbp[S];

    float W[16];
    #pragma unroll
    for (int i = 0; i < 16; i++) W[i] = 0.f;

    float Nt = 0.f, m1P = 0.f, D2 = 0.f;
    __syncthreads();

    for (int tb = 0; tb < TT; tb += 16) {
        #pragma unroll
        for (int p = 0; p < 16; p++) {
            const int t_lo = p;
            int t = tb + p;
            const int par = p & 1, parP = par ^ 1;
            float lb2 = (t + 2 < TT) ? lbp[(size_t)(t + 2) * S] : 0.f;  // distance-2 prefetch

            float m1, f, cW, cE;
            if (t_lo == 0 && tb == 0) {
                m1 = LOGPI2 + LD1 + lb;
                Nt = LOGPI2 + sBm[0];
                f  = 0.f;
                cW = ex2f(LOGPI2 + lb - m1);            // etr treated as 1 at t=0
                cE = ex2f(m1 - Nt);
            } else {
                float mp = fmaxf(fmaxf(sMk[parP][0], sMk[parP][1]),
                                 fmaxf(sMk[parP][2], sMk[parP][3]));
                float MA  = Nt + lg2f(mp);              // exact max alpha_{t-1}
                float NtN = MA + sBm[t];
                m1 = MA + mdj + lb;                     // mdj = fmax(LD1,dmax)+1
                f  = ex2f(m1P + lb - m1);               // window rescale
                cW = ex2f(Nt + lb - m1);                // wnew = etr * cW
                cE = ex2f(m1 - NtN);                    // e = dfull * cE
                Nt = NtN;
            }
            m1P = m1;

            // ---- dot e_{t-1} . A over this thread's s'-half (skipped value at t=0: sE stale=garbage?
            //      at t=0 the dot result is multiplied into wnew only via etr*cW; handle with etr=1) ----
            float etr;
            if (t_lo == 0 && tb == 0) {
                etr = 1.f;
            } else {
                const float4* ep = (const float4*)(sE[parP] + g * 32);
                float a0=0.f,a1=0.f,a2=0.f,a3=0.f,a4=0.f,a5=0.f,a6=0.f,a7=0.f;
                #pragma unroll
                for (int j4 = 0; j4 < 8; j4 += 2) {
                    float4 e0 = ep[j4], e1 = ep[j4 + 1];
                    a0 = fmaf(e0.x, rA[j4*4+0], a0);
                    a1 = fmaf(e0.y, rA[j4*4+1], a1);
                    a2 = fmaf(e0.z, rA[j4*4+2], a2);
                    a3 = fmaf(e0.w, rA[j4*4+3], a3);
                    a4 = fmaf(e1.x, rA[j4*4+4], a4);
                    a5 = fmaf(e1.y, rA[j4*4+5], a5);
                    a6 = fmaf(e1.z, rA[j4*4+6], a6);
                    a7 = fmaf(e1.w, rA[j4*4+7], a7);
                }
                float ps = ((a0+a1)+(a2+a3)) + ((a4+a5)+(a6+a7));
                etr = ps + __shfl_xor_sync(0xffffffffu, ps, 1);
            }

            // ---- insert + pipelined window dot ----
            float outv = W[p];                           // leaving entry (crosses g0->g1)
            float inv_ = __shfl_xor_sync(0xffffffffu, outv, 1);
            float new_g = (g == 0) ? etr * cW : inv_ * f;
            float dpart = fmaf(new_g, eLD[0], f * D2);
            float dfull = dpart + __shfl_xor_sync(0xffffffffu, dpart, 1);
            float e = dfull * cE;
            if (g == 0) sE[par][s] = e;
            unsigned k = __reduce_max_sync(0xffffffffu, __float_as_uint(e));
            if (lane == 0) sMk[par][w] = __uint_as_float(k);

            // ---- ring rescale + D2 for next step (off chain) ----
            #pragma unroll
            for (int r = 0; r < 16; r++)
                W[r] = (r == p) ? new_g : W[r] * f;
            float d0 = 0.f, d1 = 0.f, d2a = 0.f, d3 = 0.f;
            #pragma unroll
            for (int i = 0; i <= 14; i++) {
                float v = W[(p - i) & 15];
                if ((i & 3) == 0)      d0  = fmaf(v, eLD[i + 1], d0);
                else if ((i & 3) == 1) d1  = fmaf(v, eLD[i + 1], d1);
                else if ((i & 3) == 2) d2a = fmaf(v, eLD[i + 1], d2a);
                else                   d3  = fmaf(v, eLD[i + 1], d3);
            }
            D2 = (d0 + d1) + (d2a + d3);

            lb = lb1; lb1 = lb2;
            __syncthreads();
        }
    }
    if (tid == 0) {
        float ssum = 0.f;
        for (int j = 0; j < S; j++) ssum += sE[(TT - 1) & 1][j];
        out[b] = (Nt + lg2f(ssum)) * LN2;
    }
}

// ---------------- launch ----------------
extern "C" void kernel_launch(void* const* d_in, const int* in_sizes, int n_in,
                              void* d_out, int out_size) {
    const float* x        = (const float*)d_in[0];
    const float* context  = (const float*)d_in[1];
    const float* A_logits = (const float*)d_in[2];
    const float* D_logits = (const float*)d_in[3];
    const float* mu       = (const float*)d_in[4];
    const float* log_var  = (const float*)d_in[5];
    const float* tA_w1 = (const float*)d_in[6];
    const float* tA_b1 = (const float*)d_in[7];
    const float* tA_w2 = (const float*)d_in[8];
    const float* tA_b2 = (const float*)d_in[9];
    const float* tD_w1 = (const float*)d_in[10];
    const float* tD_b1 = (const float*)d_in[11];
    const float* tD_w2 = (const float*)d_in[12];
    const float* tD_b2 = (const float*)d_in[13];
    const float* tE_w1 = (const float*)d_in[14];
    const float* tE_b1 = (const float*)d_in[15];
    const float* tE_w2 = (const float*)d_in[16];
    const float* tE_b2 = (const float*)d_in[17];
    float* out = (float*)d_out;

    k_layer1<<<1280, 256>>>(context, tA_w1, tA_b1, tD_w1, tD_b1, tE_w1, tE_b1);
    k_layer2<<<1280, 256>>>(tA_w2, tA_b2, tD_w2, tD_b2, tE_w2, tE_b2);
    k_params<<<1, 64>>>(A_logits, D_logits, mu, log_var);
    dim3 gB(TT / 32, BB);
    k_logB<<<gB, 256>>>(x);
    k_bmax<<<(BB * TT + 7) / 8, 256>>>();
    k_recur<<<BB, 128>>>(out);
}